// round 13
// baseline (speedup 1.0000x reference)
#include <cuda_runtime.h>
#include <cstdint>
#include <cstddef>

// Problem constants
#define Bn 4
#define Cn 128
#define Hn 128
#define Wn 256
#define Dn 81
#define HWn (Hn * Wn)
#define TH 4        // output rows per block
#define TWt 128     // output cols per block
#define NTHREADS 256   // 8 warps: 4 rows x 2 col-halves; 2 px/thread, all 81 maps
#define CPS 2
#define NSTG (Cn / CPS)

__device__ __forceinline__ double pkd(float a, float b) {
    double d;
    asm("mov.b64 %0, {%1, %2};" : "=d"(d) : "f"(a), "f"(b));
    return d;
}
__device__ __forceinline__ void fma2(double &d, double a, double b) {
    asm("fma.rn.f32x2 %0, %1, %2, %0;" : "+d"(d) : "d"(a), "d"(b));
}
__device__ __forceinline__ float dlo(double d) { return __int_as_float(__double2loint(d)); }
__device__ __forceinline__ float dhi(double d) { return __int_as_float(__double2hiint(d)); }
__device__ __forceinline__ void cp16(void* dst_smem, const void* src, bool ok) {
    unsigned dst = (unsigned)__cvta_generic_to_shared(dst_smem);
    int sz = ok ? 16 : 0;
    asm volatile("cp.async.ca.shared.global [%0], [%1], 16, %2;" :: "r"(dst), "l"(src), "r"(sz));
}

__global__ void __launch_bounds__(NTHREADS, 1)
cost_volume_kernel(const float* __restrict__ x1,
                   const float* __restrict__ x2,
                   float* __restrict__ out)
{
    // x2 tile: rows h0-4..h0+7 (12) x 136; x1 tile: 4 x 128. Double buffered.
    __shared__ __align__(16) float x2s[2][CPS][12][136];   // 26112 B
    __shared__ __align__(16) float x1s[2][CPS][TH][TWt];   //  8192 B

    const int tid  = threadIdx.x;
    const int lane = tid & 31;
    const int warp = tid >> 5;       // 0..7
    const int row  = warp >> 1;      // output row 0..3
    const int half = warp & 1;       // col half 0..1
    const int p0   = 64 * half + 2 * lane;   // first pixel (even)

    const int w0 = blockIdx.x * TWt;
    const int h0 = blockIdx.y * TH;
    const int bb = blockIdx.z;

    // even-dj accumulators: [di 0..8][e 0..4] f32x2 over 2 px
    double accE[45];
    // odd-dj accumulators: [di][o 0..3][px 0..1] scalars
    float  accO[72];
#pragma unroll
    for (int i = 0; i < 45; ++i) accE[i] = 0.0;
#pragma unroll
    for (int i = 0; i < 72; ++i) accO[i] = 0.0f;

    // ---------- hoisted loader state: 3 chunk slots over 256 threads ----------
    // x2 chunks ids [0,408) = 12 rows x 34; x1 chunks ids [408,536) = 4 rows x 32
    unsigned  so[3];
    long long gofs[3];
    bool okf[3], act[3], sx1[3];
#pragma unroll
    for (int s = 0; s < 3; ++s) {
        int id = tid + s * NTHREADS;
        act[s] = false; okf[s] = false; sx1[s] = false; so[s] = 0; gofs[s] = 0;
        if (id < 408) {
            int rw = id / 34, c4 = id - rw * 34;
            int hs = h0 - 4 + rw, ws = w0 - 4 + c4 * 4;
            okf[s] = ((unsigned)hs < (unsigned)Hn) && ((unsigned)ws < (unsigned)Wn);
            gofs[s] = okf[s] ? (long long)(hs * Wn + ws) * 4 : 0;
            so[s] = (unsigned)(rw * 136 + c4 * 4) * 4;
            act[s] = true;
        } else if (id < 536) {
            int j = id - 408;
            int rw = j >> 5, c4 = j & 31;
            okf[s] = true; sx1[s] = true;
            gofs[s] = (long long)((h0 + rw) * Wn + w0 + c4 * 4) * 4;
            so[s] = (unsigned)(rw * TWt + c4 * 4) * 4;
            act[s] = true;
        }
    }
    const char* gp[3];
#pragma unroll
    for (int s = 0; s < 3; ++s)
        gp[s] = (const char*)((sx1[s] ? x1 : x2) + (size_t)bb * Cn * HWn) + gofs[s];

    auto load_ch = [&](int buf, int slot) {
#pragma unroll
        for (int s = 0; s < 3; ++s) {
            if (act[s]) {
                char* dst = (sx1[s] ? (char*)&x1s[buf][slot][0][0]
                                    : (char*)&x2s[buf][slot][0][0]) + so[s];
                cp16(dst, gp[s], okf[s]);
                gp[s] += (size_t)HWn * 4;
            }
        }
    };

    load_ch(0, 0);
    load_ch(0, 1);
    asm volatile("cp.async.commit_group;");

#pragma unroll 1
    for (int t = 0; t < NSTG; ++t) {
        const int buf = t & 1;
        if (t + 1 < NSTG) {
            load_ch(buf ^ 1, 0);
            load_ch(buf ^ 1, 1);
            asm volatile("cp.async.commit_group;");
            asm volatile("cp.async.wait_group 1;");
        } else {
            asm volatile("cp.async.wait_group 0;");
        }
        __syncthreads();

#pragma unroll
        for (int slot = 0; slot < CPS; ++slot) {
            // x1 pair for this thread's 2 pixels (8B-aligned LDS.64)
            double xp = *reinterpret_cast<const double*>(&x1s[buf][slot][row][p0]);
            float x0 = dlo(xp), x1v = dhi(xp);

            // x2 window base: tile col index p0 (pixel p0 has tile col p0+4; window
            // starts at p0+4-4 = p0). 8B-aligned since p0 even.
            const char* base = (const char*)&x2s[buf][slot][0][0]
                             + (unsigned)row * (136u * 4u) + (unsigned)p0 * 4u;
#pragma unroll
            for (int rr = 0; rr < 9; ++rr) {   // di = rr - 4, tile row = row + rr
                const double* rp = reinterpret_cast<const double*>(base + rr * (136 * 4));
                double d0 = rp[0], d1 = rp[1], d2 = rp[2], d3 = rp[3], d4 = rp[4];
                double dd[5] = {d0, d1, d2, d3, d4};
                // even dj = 2e-4: operand pair = dd[e] (aligned, zero packing)
#pragma unroll
                for (int e = 0; e < 5; ++e)
                    fma2(accE[rr * 5 + e], xp, dd[e]);
                // odd dj = 2o-3: free register-half aliases
#pragma unroll
                for (int o = 0; o < 4; ++o) {
                    accO[(rr * 4 + o) * 2 + 0] = fmaf(x0,  dhi(dd[o]),     accO[(rr * 4 + o) * 2 + 0]);
                    accO[(rr * 4 + o) * 2 + 1] = fmaf(x1v, dlo(dd[o + 1]), accO[(rr * 4 + o) * 2 + 1]);
                }
            }
        }
        __syncthreads();
    }

    // ---------- epilogue: scale + scatter (STG.64 per map) ----------
    const float inv = 1.0f / 81.0f;
    const int h = h0 + row;
    const size_t obase = ((size_t)bb * Dn * Hn + h) * Wn + w0 + p0;
#pragma unroll
    for (int rr = 0; rr < 9; ++rr) {
        const int di = rr - 4;
#pragma unroll
        for (int e = 0; e < 5; ++e) {
            const int dj = 2 * e - 4;
            const int tt = 9 * di + dj;
            const int k = (81 - tt) % 81;
            double a = accE[rr * 5 + e];
            double o = pkd(dlo(a) * inv, dhi(a) * inv);
            *reinterpret_cast<double*>(out + obase + (size_t)k * (Hn * Wn)) = o;
        }
#pragma unroll
        for (int oj = 0; oj < 4; ++oj) {
            const int dj = 2 * oj - 3;
            const int tt = 9 * di + dj;
            const int k = (81 - tt) % 81;
            double o = pkd(accO[(rr * 4 + oj) * 2 + 0] * inv,
                           accO[(rr * 4 + oj) * 2 + 1] * inv);
            *reinterpret_cast<double*>(out + obase + (size_t)k * (Hn * Wn)) = o;
        }
    }
}

extern "C" void kernel_launch(void* const* d_in, const int* in_sizes, int n_in,
                              void* d_out, int out_size) {
    const float* x1 = (const float*)d_in[0];
    const float* x2 = (const float*)d_in[1];
    float* out = (float*)d_out;
    dim3 grid(Wn / TWt, Hn / TH, Bn);   // (2, 32, 4) = 256 blocks
    cost_volume_kernel<<<grid, NTHREADS>>>(x1, x2, out);
}